// round 6
// baseline (speedup 1.0000x reference)
#include <cuda_runtime.h>

// Closed-form normalization constants.
#define Y00f  0.28209479177387814f    // 1/(2*sqrt(pi))
#define N10f  0.48860251190291992f    // sqrt(3/(4pi))
#define N20f  0.63078313050504001f    // sqrt(5/(4pi))
#define C21f  (-1.09254843059207907f) // -(1/2)*sqrt(15/pi)
#define C22f  0.54627421529603953f    // (1/4)*sqrt(15/pi)
#define K20f  0.35355339059327379f    // 1/(2*sqrt(2))
#define K21f  0.20412414523193152f    // 1/(2*sqrt(6))
#define K30f  0.06415002990995843f    // 1/(9*sqrt(3))
#define K31f  0.04536092116208279f    // sqrt(1/486)
#define K32f  0.02028602047074832f    // sqrt(8/19440)

typedef unsigned long long u64;

__device__ __forceinline__ u64 pk(float lo, float hi) {
    u64 r; asm("mov.b64 %0,{%1,%2};" : "=l"(r) : "f"(lo), "f"(hi)); return r;
}
__device__ __forceinline__ void upk(u64 v, float& lo, float& hi) {
    asm("mov.b64 {%0,%1},%2;" : "=f"(lo), "=f"(hi) : "l"(v));
}
__device__ __forceinline__ u64 f2mul(u64 a, u64 b) {
    u64 d; asm("mul.rn.f32x2 %0,%1,%2;" : "=l"(d) : "l"(a), "l"(b)); return d;
}
__device__ __forceinline__ u64 f2fma(u64 a, u64 b, u64 c) {
    u64 d; asm("fma.rn.f32x2 %0,%1,%2,%3;" : "=l"(d) : "l"(a), "l"(b), "l"(c)); return d;
}
__device__ __forceinline__ u64 f2add(u64 a, u64 b) {
    u64 d; asm("add.rn.f32x2 %0,%1,%2;" : "=l"(d) : "l"(a), "l"(b)); return d;
}

// Per-point scalar prep: MUFU ops + constant-immediate ops (FFMA-imm rt=1).
struct Prep { float r, t, ct, st, cp, sp, rho, tmr, fmr, l30, nspsq, ct2t; };

__device__ __forceinline__ Prep prep(float r, float th, float ph) {
    Prep p;
    p.r = r;
    __sincosf(th, &p.st, &p.ct);
    __sincosf(ph, &p.sp, &p.cp);
    p.t     = __expf(r * (-1.0f / 6.0f));      // e^{-r/6}
    p.rho   = r * (2.0f / 3.0f);
    p.tmr   = 2.0f - r;
    p.fmr   = 4.0f - p.rho;
    p.l30   = fmaf(p.rho - 6.0f, p.rho, 6.0f); // rho^2 - 6 rho + 6
    p.nspsq = p.sp * (-p.sp);                  // -sin^2(phi)
    p.ct2t  = fmaf(p.ct * p.ct, 1.5f, -0.5f);  // (3cos^2-1)/2
    return p;
}

// Packed evaluation of two points with register-resident coefficients.
__device__ __forceinline__ u64 eval_pair(const Prep& p0, const Prep& p1, const u64* a) {
    u64 R   = pk(p0.r,   p1.r),   T    = pk(p0.t,    p1.t);
    u64 CT  = pk(p0.ct,  p1.ct),  ST   = pk(p0.st,   p1.st);
    u64 CP  = pk(p0.cp,  p1.cp),  SP   = pk(p0.sp,   p1.sp);
    u64 RHO = pk(p0.rho, p1.rho), TMR  = pk(p0.tmr,  p1.tmr);
    u64 FMR = pk(p0.fmr, p1.fmr), L30  = pk(p0.l30,  p1.l30);
    u64 NSQ = pk(p0.nspsq, p1.nspsq), CT2T = pk(p0.ct2t, p1.ct2t);

    u64 T2 = f2mul(T, T), T3 = f2mul(T2, T), T6 = f2mul(T3, T3);
    u64 G3 = f2mul(FMR, RHO);           // (4-rho)*rho
    u64 Q  = f2mul(RHO, RHO);           // rho^2
    u64 C2P  = f2fma(CP, CP, NSQ);      // cos(2phi)
    u64 SPCP = f2mul(SP, CP);
    u64 S2P  = f2add(SPCP, SPCP);       // sin(2phi)
    u64 CTST = f2mul(CT, ST), ST2 = f2mul(ST, ST);

    // n=2 block (×t3)
    u64 X1 = f2fma(CP, a[3], f2mul(SP, a[4]));
    X1     = f2fma(CT, a[2], f2mul(ST, X1));
    u64 B3 = f2fma(TMR, a[1], f2mul(R, X1));

    // n=3, l=0..1 block (×t2)
    u64 X2 = f2fma(CP, a[7], f2mul(SP, a[8]));
    X2     = f2fma(CT, a[6], f2mul(ST, X2));
    u64 P2 = f2fma(L30, a[5], f2mul(G3, X2));

    // n=3, l=2 block
    u64 Y = f2fma(CP, a[10], f2mul(SP, a[11]));
    Y     = f2mul(CTST, Y);
    u64 Z = f2fma(C2P, a[12], f2mul(S2P, a[13]));
    u64 W = f2fma(ST2, Z, f2fma(CT2T, a[9], Y));
    u64 B2 = f2fma(Q, W, P2);

    return f2fma(T6, a[0], f2fma(T3, B3, f2mul(T2, B2)));
}

__global__ __launch_bounds__(128)
void orbital_eval_kernel(const float* __restrict__ pos,
                         const float* __restrict__ coeffs,
                         float* __restrict__ out,
                         int n4, int n) {
    int tid0   = blockIdx.x * blockDim.x + threadIdx.x;
    int stride = gridDim.x * blockDim.x;

    // Coefficient prep once per thread (amortized over the grid-stride loop).
    float c[14];
#pragma unroll
    for (int k = 0; k < 14; k++) c[k] = __ldg(&coeffs[k]);
    float ac[14];
    ac[0]  =  Y00f * 2.0f * c[0];
    ac[1]  =  Y00f * K20f * c[1];
    ac[2]  =  N10f * K21f * c[3];
    ac[3]  = -N10f * K21f * c[4];
    ac[4]  = -N10f * K21f * c[2];
    ac[5]  =  Y00f * K30f * c[5];
    ac[6]  =  N10f * K31f * c[7];
    ac[7]  = -N10f * K31f * c[8];
    ac[8]  = -N10f * K31f * c[6];
    ac[9]  =  N20f * K32f * c[11];
    ac[10] =  C21f * K32f * c[12];
    ac[11] =  C21f * K32f * c[10];
    ac[12] =  C22f * K32f * c[13];
    ac[13] =  C22f * K32f * c[9];
    u64 a[14];
#pragma unroll
    for (int k = 0; k < 14; k++) a[k] = pk(ac[k], ac[k]);

    const float4* p4 = reinterpret_cast<const float4*>(pos);
    float4* o4       = reinterpret_cast<float4*>(out);

    int i = tid0;
    if (i < n4) {
        // Prologue load (3x LDG.128 = 4 points).
        float4 v0 = p4[3 * i + 0];
        float4 v1 = p4[3 * i + 1];
        float4 v2 = p4[3 * i + 2];

        while (true) {
            // Prefetch NEXT iteration's points before computing the current ones,
            // so the loads stay outstanding through the whole compute body.
            int j = i + stride;
            bool have = (j < n4);
            float4 w0, w1, w2;
            if (have) {
                w0 = p4[3 * j + 0];
                w1 = p4[3 * j + 1];
                w2 = p4[3 * j + 2];
            }

            // Evaluate 4 current points: (v0.x,v0.y,v0.z) (v0.w,v1.x,v1.y)
            //                            (v1.z,v1.w,v2.x) (v2.y,v2.z,v2.w)
            Prep q0 = prep(v0.x, v0.y, v0.z);
            Prep q1 = prep(v0.w, v1.x, v1.y);
            u64 r01 = eval_pair(q0, q1, a);
            Prep q2 = prep(v1.z, v1.w, v2.x);
            Prep q3 = prep(v2.y, v2.z, v2.w);
            u64 r23 = eval_pair(q2, q3, a);

            float4 o;
            upk(r01, o.x, o.y);
            upk(r23, o.z, o.w);
            o4[i] = o;

            if (!have) break;
            v0 = w0; v1 = w1; v2 = w2;
            i = j;
        }
    }

    // Scalar tail (n % 4 != 0).
    int tail = n - n4 * 4;
    if (tid0 < tail) {
        int idx = n4 * 4 + tid0;
        Prep p = prep(pos[3 * idx], pos[3 * idx + 1], pos[3 * idx + 2]);
        u64 rr = eval_pair(p, p, a);
        float lo, hi; upk(rr, lo, hi);
        out[idx] = lo;
    }
}

extern "C" void kernel_launch(void* const* d_in, const int* in_sizes, int n_in,
                              void* d_out, int out_size) {
    const float* pos    = (const float*)d_in[0];   // (2048, 4096, 3) fp32
    const float* coeffs = (const float*)d_in[1];   // (14,) fp32
    float* out          = (float*)d_out;           // (2048, 4096) fp32

    int n  = out_size;
    int n4 = n / 4;

    const int threads = 128;
    const int iters   = 4;   // grid-stride iterations per thread
    long long groups  = (n4 > 0) ? n4 : 1;
    int blocks = (int)((groups + (long long)threads * iters - 1) / ((long long)threads * iters));
    if (blocks < 1) blocks = 1;

    orbital_eval_kernel<<<blocks, threads>>>(pos, coeffs, out, n4, n);
}

// round 7
// speedup vs baseline: 1.0012x; 1.0012x over previous
#include <cuda_runtime.h>

// Closed-form normalization constants.
#define Y00f  0.28209479177387814f    // 1/(2*sqrt(pi))
#define N10f  0.48860251190291992f    // sqrt(3/(4pi))
#define N20f  0.63078313050504001f    // sqrt(5/(4pi))
#define C21f  (-1.09254843059207907f) // -(1/2)*sqrt(15/pi)
#define C22f  0.54627421529603953f    // (1/4)*sqrt(15/pi)
#define K20f  0.35355339059327379f    // 1/(2*sqrt(2))
#define K21f  0.20412414523193152f    // 1/(2*sqrt(6))
#define K30f  0.06415002990995843f    // 1/(9*sqrt(3))
#define K31f  0.04536092116208279f    // sqrt(1/486)
#define K32f  0.02028602047074832f    // sqrt(8/19440)

typedef unsigned long long u64;

__device__ __forceinline__ u64 pk(float lo, float hi) {
    u64 r; asm("mov.b64 %0,{%1,%2};" : "=l"(r) : "f"(lo), "f"(hi)); return r;
}
__device__ __forceinline__ void upk(u64 v, float& lo, float& hi) {
    asm("mov.b64 {%0,%1},%2;" : "=f"(lo), "=f"(hi) : "l"(v));
}
__device__ __forceinline__ u64 f2mul(u64 a, u64 b) {
    u64 d; asm("mul.rn.f32x2 %0,%1,%2;" : "=l"(d) : "l"(a), "l"(b)); return d;
}
__device__ __forceinline__ u64 f2fma(u64 a, u64 b, u64 c) {
    u64 d; asm("fma.rn.f32x2 %0,%1,%2,%3;" : "=l"(d) : "l"(a), "l"(b), "l"(c)); return d;
}
__device__ __forceinline__ u64 f2add(u64 a, u64 b) {
    u64 d; asm("add.rn.f32x2 %0,%1,%2;" : "=l"(d) : "l"(a), "l"(b)); return d;
}

// 15 packed coefficient registers (lo == hi) + 1 scalar (b5s).
struct Co {
    u64 b0, b1n, b1d;            // T6 coeff; X1 addend; B3 addend
    u64 a2, a3, a4;              // n=2 l=1 angular (ct, cp, sp)
    u64 a6, a7, a8;              // n=3 l=1 angular
    u64 w9a, cw, w10, w11, w12m, w13;  // l=2 block (4/9 pre-folded)
    float b5s;                   // L30 coefficient (scalar)
};

// Per-point MUFU-only + imm-FFMA prep.
struct P8 { float r, t, ct, st, cp, sp, l30b, g3c; };

__device__ __forceinline__ P8 prep(float r, float th, float ph, float b5s) {
    P8 p;
    p.r = r;
    __sincosf(th, &p.st, &p.ct);
    __sincosf(ph, &p.sp, &p.cp);
    p.t = __expf(r * (-1.0f / 6.0f));              // e^{-r/6}
    float u = fmaf(r, 4.0f / 9.0f, -4.0f);          // imm-FFMA
    p.l30b = fmaf(u, r, 6.0f) * b5s;                // b5*((4/9)r^2-4r+6)
    p.g3c  = fmaf(r, -4.0f / 9.0f, 8.0f / 3.0f);    // (8/3)-(4/9)r
    return p;
}

// Fully packed evaluation of two points.
__device__ __forceinline__ u64 eval_pair(const P8& p0, const P8& p1, const Co& C) {
    u64 R   = pk(p0.r,    p1.r),    T   = pk(p0.t,   p1.t);
    u64 CT  = pk(p0.ct,   p1.ct),   ST  = pk(p0.st,  p1.st);
    u64 CP  = pk(p0.cp,   p1.cp),   SP  = pk(p0.sp,  p1.sp);
    u64 L30B = pk(p0.l30b, p1.l30b), G3C = pk(p0.g3c, p1.g3c);

    u64 T2 = f2mul(T, T), T3 = f2mul(T2, T), T6 = f2mul(T3, T3);
    u64 R2 = f2mul(R, R);
    u64 SPSP = f2mul(SP, SP), SPCP = f2mul(SP, CP);
    u64 CTCT = f2mul(CT, CT), ST2 = f2mul(ST, ST), CTST = f2mul(CT, ST);

    // n=2 block: B3 = r*(X1 + b1n) + b1d
    u64 X1 = f2fma(CT, C.a2, f2mul(ST, f2fma(CP, C.a3, f2mul(SP, C.a4))));
    u64 B3 = f2fma(R, f2add(X1, C.b1n), C.b1d);

    // n=3 l=0..1: P2 = L30B + r*g3c*X2
    u64 X2 = f2fma(CT, C.a6, f2mul(ST, f2fma(CP, C.a7, f2mul(SP, C.a8))));
    u64 G3 = f2mul(R, G3C);
    u64 P2 = f2fma(G3, X2, L30B);

    // n=3 l=2 (rho^2=(4/9)r^2 folded into w-consts):
    u64 Y = f2fma(CP, C.w10, f2mul(SP, C.w11));
    u64 Z = f2fma(SPCP, C.w13, f2mul(SPSP, C.w12m));
    u64 W = f2fma(ST2, Z, f2fma(CTST, Y, f2fma(CTCT, C.w9a, C.cw)));
    u64 B2 = f2fma(R2, W, P2);

    return f2fma(T6, C.b0, f2fma(T3, B3, f2mul(T2, B2)));
}

__global__ __launch_bounds__(128)
void orbital_eval_kernel(const float* __restrict__ pos,
                         const float* __restrict__ coeffs,
                         float* __restrict__ out,
                         int n4, int n) {
    int tid0   = blockIdx.x * blockDim.x + threadIdx.x;
    int stride = gridDim.x * blockDim.x;

    // Per-thread coefficient fold (amortized over the grid-stride loop).
    float c[14];
#pragma unroll
    for (int k = 0; k < 14; k++) c[k] = __ldg(&coeffs[k]);

    Co C;
    {
        float b0  =  2.0f * Y00f * c[0];
        float b1  =  Y00f * K20f * c[1];
        float a2  =  N10f * K21f * c[3];
        float a3  = -N10f * K21f * c[4];
        float a4  = -N10f * K21f * c[2];
        float a6  =  N10f * K31f * c[7];
        float a7  = -N10f * K31f * c[8];
        float a8  = -N10f * K31f * c[6];
        float n2  =  N20f * K32f * c[11];
        float q12 =  (4.0f / 9.0f) * C21f * K32f * c[12];
        float q10 =  (4.0f / 9.0f) * C21f * K32f * c[10];
        float e13 =  (4.0f / 9.0f) * C22f * K32f * c[13];
        float e9  =  (8.0f / 9.0f) * C22f * K32f * c[9];
        float w9a = (2.0f / 3.0f) * n2 - e13;          // ct^2 coeff (w12s folded)
        float cw  = -(2.0f / 9.0f) * n2 + e13;         // constant term
        C.b0  = pk(b0, b0);
        C.b1n = pk(-b1, -b1);
        C.b1d = pk(2.0f * b1, 2.0f * b1);
        C.a2 = pk(a2, a2); C.a3 = pk(a3, a3); C.a4 = pk(a4, a4);
        C.a6 = pk(a6, a6); C.a7 = pk(a7, a7); C.a8 = pk(a8, a8);
        C.w9a = pk(w9a, w9a); C.cw = pk(cw, cw);
        C.w10 = pk(q12, q12); C.w11 = pk(q10, q10);
        C.w12m = pk(-2.0f * e13, -2.0f * e13); C.w13 = pk(e9, e9);
        C.b5s = Y00f * K30f * c[5];
    }

    const float4* p4 = reinterpret_cast<const float4*>(pos);
    float4* o4       = reinterpret_cast<float4*>(out);

    int i = tid0;
    if (i < n4) {
        float4 v0 = p4[3 * i + 0];
        float4 v1 = p4[3 * i + 1];
        float4 v2 = p4[3 * i + 2];

        while (true) {
            // Prefetch next iteration's points before computing current ones.
            int j = i + stride;
            bool have = (j < n4);
            float4 w0, w1, w2;
            if (have) {
                w0 = p4[3 * j + 0];
                w1 = p4[3 * j + 1];
                w2 = p4[3 * j + 2];
            }

            P8 q0 = prep(v0.x, v0.y, v0.z, C.b5s);
            P8 q1 = prep(v0.w, v1.x, v1.y, C.b5s);
            u64 r01 = eval_pair(q0, q1, C);
            P8 q2 = prep(v1.z, v1.w, v2.x, C.b5s);
            P8 q3 = prep(v2.y, v2.z, v2.w, C.b5s);
            u64 r23 = eval_pair(q2, q3, C);

            float4 o;
            upk(r01, o.x, o.y);
            upk(r23, o.z, o.w);
            __stcs(&o4[i], o);   // streaming store: keep input L2-resident

            if (!have) break;
            v0 = w0; v1 = w1; v2 = w2;
            i = j;
        }
    }

    // Scalar tail (n % 4 != 0).
    int tail = n - n4 * 4;
    if (tid0 < tail) {
        int idx = n4 * 4 + tid0;
        P8 p = prep(pos[3 * idx], pos[3 * idx + 1], pos[3 * idx + 2], C.b5s);
        u64 rr = eval_pair(p, p, C);
        float lo, hi; upk(rr, lo, hi);
        out[idx] = lo;
    }
}

extern "C" void kernel_launch(void* const* d_in, const int* in_sizes, int n_in,
                              void* d_out, int out_size) {
    const float* pos    = (const float*)d_in[0];   // (2048, 4096, 3) fp32
    const float* coeffs = (const float*)d_in[1];   // (14,) fp32
    float* out          = (float*)d_out;           // (2048, 4096) fp32

    int n  = out_size;
    int n4 = n / 4;

    const int threads = 128;
    const int iters   = 6;   // grid-stride iterations per thread
    long long groups  = (n4 > 0) ? n4 : 1;
    int blocks = (int)((groups + (long long)threads * iters - 1) / ((long long)threads * iters));
    if (blocks < 1) blocks = 1;

    orbital_eval_kernel<<<blocks, threads>>>(pos, coeffs, out, n4, n);
}